// round 8
// baseline (speedup 1.0000x reference)
#include <cuda_runtime.h>
#include <cuda_bf16.h>
#include <math.h>
#include <stdint.h>

#define RB 4
#define CC 256
#define HWSZ 4096
#define OC2 18
#define PW 68
#define PHW 4624            // 68*68
#define PBASE 138           // 2*68 + 2

// ---------------- smem layout (bytes, dynamic) ------------------------------
// K-block = 32 ck. A tile 256x32 bf16 = 16KB (hi) + 16KB (lo) per stage.
#define SM_A0   0
#define SM_A1   32768
// B tile 128x32 bf16 = 8KB hi + 8KB lo per stage.
#define SM_B0   65536
#define SM_B1   81920
#define SM_IDX  98304       // int[1152]
#define SM_WY   102912      // float[1152]
#define SM_WX   107520      // float[1152]
#define SM_TOTAL 112128

// 64B-row swizzle: row*64 + (seg16B ^ ((row&3)<<4) ^ ((row&4)<<2))
#define SW64(row, colb) (((uint32_t)(row) << 6) + \
    ((uint32_t)(colb) ^ (((uint32_t)(row) & 3) << 4) ^ (((uint32_t)(row) & 4) << 2)))

// ---------------- scratch (device globals; no allocations allowed) ----------
__device__ float g_padA[4734976];    // 4*256*68*68 padded planes
__device__ float g_padB[4734976];
// main weights: [r][kb32=kk*8+cb (72)][oc (256)][j (32)], c = cb*32+j
__device__ __align__(16) __nv_bfloat16 g_whi[2359296];
__device__ __align__(16) __nv_bfloat16 g_wlo[2359296];
// offset weights: [r][kb32 (72)][ocp (32)][j (32)]
__device__ __align__(16) __nv_bfloat16 g_owhi[294912];
__device__ __align__(16) __nv_bfloat16 g_owlo[294912];

// ---------------- PTX helpers ----------------------------------------------
static __device__ __forceinline__ uint32_t smem_u32(const void* p) {
    uint32_t a;
    asm("{ .reg .u64 t; cvta.to.shared.u64 t, %1; cvt.u32.u64 %0, t; }" : "=r"(a) : "l"(p));
    return a;
}

#define LDSM4(r, a) \
    asm volatile("ldmatrix.sync.aligned.m8n8.x4.shared.b16 {%0,%1,%2,%3}, [%4];" \
                 : "=r"((r)[0]), "=r"((r)[1]), "=r"((r)[2]), "=r"((r)[3]) : "r"(a))

#define LDSM2(r, a) \
    asm volatile("ldmatrix.sync.aligned.m8n8.x2.shared.b16 {%0,%1}, [%2];" \
                 : "=r"((r)[0]), "=r"((r)[1]) : "r"(a))

#define MMA16816(c, a, b0, b1) \
    asm volatile("mma.sync.aligned.m16n8k16.row.col.f32.bf16.bf16.f32 " \
                 "{%0,%1,%2,%3}, {%4,%5,%6,%7}, {%8,%9}, {%0,%1,%2,%3};" \
                 : "+f"((c)[0]), "+f"((c)[1]), "+f"((c)[2]), "+f"((c)[3]) \
                 : "r"((a)[0]), "r"((a)[1]), "r"((a)[2]), "r"((a)[3]), \
                   "r"(b0), "r"(b1))

#define CP16(dst, src) \
    asm volatile("cp.async.cg.shared.global [%0], [%1], 16;" :: "r"(dst), "l"(src))
#define CP_COMMIT() asm volatile("cp.async.commit_group;")
#define CP_WAIT0()  asm volatile("cp.async.wait_group 0;")

// ---------------- prep kernels ----------------------------------------------
__global__ void pad_input_kernel(const float* __restrict__ x,
                                 float* __restrict__ pA, float* __restrict__ pB) {
    int i = blockIdx.x * 256 + threadIdx.x;
    if (i >= 4734976) return;
    int plane = i / PHW, rem = i - plane * PHW;
    int h = rem / PW - 2, w = rem % PW - 2;
    float v = 0.f;
    if (h >= 0 && h < 64 && w >= 0 && w < 64) v = x[plane * HWSZ + h * 64 + w];
    pA[i] = v;
    pB[i] = 0.f;
}

__global__ void prep_w_kernel(const float* __restrict__ w,
                              __nv_bfloat16* __restrict__ whi,
                              __nv_bfloat16* __restrict__ wlo) {
    int idx = blockIdx.x * 256 + threadIdx.x;
    if (idx >= 2359296) return;
    int r = idx / 589824;
    int rem = idx - r * 589824;
    int kb = rem >> 13;          // 0..71
    int rem2 = rem & 8191;
    int oc = rem2 >> 5;
    int j = rem2 & 31;
    int kk = kb >> 3;
    int c = ((kb & 7) << 5) + j;
    float v = w[(((r * 256 + oc) * 256 + c) * 9) + kk];
    __nv_bfloat16 h = __float2bfloat16_rn(v);
    whi[idx] = h;
    wlo[idx] = __float2bfloat16_rn(v - __bfloat162float(h));
}

__global__ void prep_offw_kernel(const float* __restrict__ offw,
                                 __nv_bfloat16* __restrict__ owhi,
                                 __nv_bfloat16* __restrict__ owlo) {
    int idx = blockIdx.x * 256 + threadIdx.x;
    if (idx >= 294912) return;
    int r = idx / 73728;
    int rem = idx - r * 73728;
    int kb = rem >> 10;          // 0..71
    int rem2 = rem & 1023;
    int ocp = rem2 >> 5;
    int j = rem2 & 31;
    int kk = kb >> 3;
    int c = ((kb & 7) << 5) + j;
    float v = (ocp < OC2) ? offw[((r * OC2 + ocp) * 256 + c) * 9 + kk] : 0.f;
    __nv_bfloat16 h = __float2bfloat16_rn(v);
    owhi[idx] = h;
    owlo[idx] = __float2bfloat16_rn(v - __bfloat162float(h));
}

// ---------------- staging helpers -------------------------------------------
// A tile: 256 oc x 32 ck = 1024 16B chunks (hi), same for lo.
static __device__ __forceinline__ void stageA2(uint32_t dst,
        const __nv_bfloat16* whi, const __nv_bfloat16* wlo, int kb, int tid) {
    const char* ah = (const char*)whi + ((size_t)kb << 14);
    const char* al = (const char*)wlo + ((size_t)kb << 14);
#pragma unroll
    for (int t = 0; t < 2; ++t) {
        int i = tid + (t << 9);
        uint32_t o = SW64(i >> 2, (i & 3) << 4);
        CP16(dst + o, ah + ((size_t)i << 4));
        CP16(dst + 16384 + o, al + ((size_t)i << 4));
    }
}

static __device__ __forceinline__ void stageA1(uint32_t dst,
        const __nv_bfloat16* owhi, const __nv_bfloat16* owlo, int kb, int tid) {
    if (tid < 128) {
        uint32_t o = SW64(tid >> 2, (tid & 3) << 4);
        CP16(dst + o, (const char*)owhi + ((size_t)kb << 11) + (tid << 4));
        CP16(dst + 16384 + o, (const char*)owlo + ((size_t)kb << 11) + (tid << 4));
    }
}

static __device__ __forceinline__ void cvt_pair(float v0, float v1,
        uint32_t& hp, uint32_t& lp) {
    __nv_bfloat162 h2, l2;
    h2.x = __float2bfloat16_rn(v0);
    h2.y = __float2bfloat16_rn(v1);
    l2.x = __float2bfloat16_rn(v0 - __bfloat162float(h2.x));
    l2.y = __float2bfloat16_rn(v1 - __bfloat162float(h2.y));
    hp = *(uint32_t*)&h2;
    lp = *(uint32_t*)&l2;
}

static __device__ __forceinline__ void storeB(char* smem, uint32_t bbuf,
        int px, int cg, const uint32_t* hp, const uint32_t* lp) {
    uint32_t o = SW64(px, cg << 4);
    *(uint4*)(smem + bbuf + o) = make_uint4(hp[0], hp[1], hp[2], hp[3]);
    *(uint4*)(smem + bbuf + 8192 + o) = make_uint4(lp[0], lp[1], lp[2], lp[3]);
}

// im2col staging (phase 1): 8 channels per thread
static __device__ __forceinline__ void sampleB1(char* smem, uint32_t bbuf,
        const float* __restrict__ xpad, int b, int kb, int px, int cg,
        int hpx, int wpx) {
    int kk = kb >> 3;
    const float* xb = xpad + ((size_t)(b * 256) + ((kb & 7) << 5) + (cg << 3)) * PHW
                    + (hpx + kk / 3 + 1) * PW + (wpx + kk % 3 + 1);
    uint32_t hp[4], lp[4];
#pragma unroll
    for (int jj = 0; jj < 4; ++jj) {
        float v0 = xb[(size_t)(jj << 1) * PHW];
        float v1 = xb[(size_t)((jj << 1) + 1) * PHW];
        cvt_pair(v0, v1, hp[jj], lp[jj]);
    }
    storeB(smem, bbuf, px, cg, hp, lp);
}

// deformed sampling staging (phase 2): 8 channels per thread
static __device__ __forceinline__ void sampleB2(char* smem, uint32_t bbuf,
        const float* __restrict__ xpad, int b, int kb, int px, int cg) {
    int kk = kb >> 3;
    int mi = kk * 128 + px;
    int idx0 = ((const int*)(smem + SM_IDX))[mi];
    float wy = ((const float*)(smem + SM_WY))[mi];
    float wx = ((const float*)(smem + SM_WX))[mi];
    float w01 = (1.f - wy) * wx;
    float w00 = (1.f - wy) - w01;
    float w11 = wy * wx;
    float w10 = wy - w11;
    const float* xb = xpad + ((size_t)(b * 256) + ((kb & 7) << 5) + (cg << 3)) * PHW + idx0;
    uint32_t hp[4], lp[4];
#pragma unroll
    for (int jj = 0; jj < 4; ++jj) {
        const float* p0 = xb + (size_t)(jj << 1) * PHW;
        const float* p1 = p0 + PHW;
        float v0 = fmaf(w11, p0[PW + 1], fmaf(w10, p0[PW], fmaf(w01, p0[1], w00 * p0[0])));
        float v1 = fmaf(w11, p1[PW + 1], fmaf(w10, p1[PW], fmaf(w01, p1[1], w00 * p1[0])));
        cvt_pair(v0, v1, hp[jj], lp[jj]);
    }
    storeB(smem, bbuf, px, cg, hp, lp);
}

// ---------------- fused layer kernel ----------------------------------------
// grid = 128 CTAs (4 batches x 32 px-tiles of 128), 512 threads / 16 warps.
__global__ __launch_bounds__(512, 1) void fused_layer_kernel(
    const float* __restrict__ xpad,
    const __nv_bfloat16* __restrict__ owhi, const __nv_bfloat16* __restrict__ owlo,
    const float* __restrict__ offbias,
    const __nv_bfloat16* __restrict__ whi, const __nv_bfloat16* __restrict__ wlo,
    float* __restrict__ outp, int pad_out)
{
    extern __shared__ char smem[];
    uint32_t sb = smem_u32(smem);
    int tid = threadIdx.x;
    int lane = tid & 31;
    int wid = tid >> 5;
    int b = blockIdx.x >> 5;
    int px0 = (blockIdx.x & 31) << 7;

    int px = tid & 127;
    int cg = tid >> 7;
    int hpx = (px0 + px) >> 6;
    int wpx = (px0 + px) & 63;

    // ================= PHASE 1: offset conv GEMM (D_off[32][128]) ==========
    float acc1[2][4];
#pragma unroll
    for (int mi = 0; mi < 2; ++mi)
#pragma unroll
        for (int q = 0; q < 4; ++q) acc1[mi][q] = 0.f;

    stageA1(sb + SM_A0, owhi, owlo, 0, tid);
    CP_COMMIT();
    sampleB1(smem, SM_B0, xpad, b, 0, px, cg, hpx, wpx);
    CP_WAIT0();
    __syncthreads();

    for (int kb = 0; kb < 72; ++kb) {
        uint32_t acur = (kb & 1) ? SM_A1 : SM_A0;
        uint32_t bcur = (kb & 1) ? SM_B1 : SM_B0;
        uint32_t anx  = (kb & 1) ? SM_A0 : SM_A1;
        uint32_t bnx  = (kb & 1) ? SM_B0 : SM_B1;
        if (kb < 71) {
            stageA1(sb + anx, owhi, owlo, kb + 1, tid);
            CP_COMMIT();
            sampleB1(smem, bnx, xpad, b, kb + 1, px, cg, hpx, wpx);
        }
        int n_base = wid << 3;
#pragma unroll
        for (int ks = 0; ks < 2; ++ks) {
            uint32_t ah1[2][4], al1[2][4], bh1[2], bl1[2];
#pragma unroll
            for (int mi = 0; mi < 2; ++mi) {
                int row = (mi << 4) + (lane & 15);
                uint32_t o = SW64(row, (ks << 5) + ((lane >> 4) << 4));
                LDSM4(ah1[mi], sb + acur + o);
                LDSM4(al1[mi], sb + acur + 16384 + o);
            }
            int brow = n_base + (lane & 7);
            uint32_t bo = SW64(brow, (ks << 5) + (((lane >> 3) & 1) << 4));
            LDSM2(bh1, sb + bcur + bo);
            LDSM2(bl1, sb + bcur + 8192 + bo);
#pragma unroll
            for (int mi = 0; mi < 2; ++mi) {
                MMA16816(acc1[mi], ah1[mi], bh1[0], bh1[1]);
                MMA16816(acc1[mi], al1[mi], bh1[0], bh1[1]);
                MMA16816(acc1[mi], ah1[mi], bl1[0], bl1[1]);
            }
        }
        CP_WAIT0();
        __syncthreads();
    }

    // write offsets to smem (reuse SM_B0 region, 16KB): offs[32][128] f32
    {
        float* offs = (float*)(smem + SM_B0);
#pragma unroll
        for (int mi = 0; mi < 2; ++mi) {
            int ocp = (mi << 4) + (lane >> 2);
            int pc = (wid << 3) + ((lane & 3) << 1);
            offs[ocp * 128 + pc] = acc1[mi][0];
            offs[ocp * 128 + pc + 1] = acc1[mi][1];
            offs[(ocp + 8) * 128 + pc] = acc1[mi][2];
            offs[(ocp + 8) * 128 + pc + 1] = acc1[mi][3];
        }
    }
    __syncthreads();

    // ---- bilinear metadata (padded addressing, clamped) ----
    {
        const float* offs = (const float*)(smem + SM_B0);
        int* sIdx = (int*)(smem + SM_IDX);
        float* sWy = (float*)(smem + SM_WY);
        float* sWx = (float*)(smem + SM_WX);
        for (int i = tid; i < 1152; i += 512) {
            int kk = i >> 7;
            int p = i & 127;
            int pix = px0 + p;
            int h = pix >> 6;
            int w = pix & 63;
            float dy = offs[((2 * kk) << 7) + p] + offbias[2 * kk];
            float dx = offs[((2 * kk + 1) << 7) + p] + offbias[2 * kk + 1];
            float py = fminf(fmaxf((float)(h + kk / 3 - 1) + dy, -1.5f), 64.5f);
            float pxx = fminf(fmaxf((float)(w + kk % 3 - 1) + dx, -1.5f), 64.5f);
            float y0f = floorf(py), x0f = floorf(pxx);
            sIdx[i] = ((int)y0f + 2) * PW + ((int)x0f + 2);
            sWy[i] = py - y0f;
            sWx[i] = pxx - x0f;
        }
    }
    __syncthreads();

    // ================= PHASE 2: deform GEMM (D[256][128]) ==================
    float acc[4][4][4];
#pragma unroll
    for (int mi = 0; mi < 4; ++mi)
#pragma unroll
        for (int nj = 0; nj < 4; ++nj)
#pragma unroll
            for (int q = 0; q < 4; ++q) acc[mi][nj][q] = 0.f;

    int m_base = (wid & 3) << 6;
    int n_base = (wid >> 2) << 5;

    stageA2(sb + SM_A0, whi, wlo, 0, tid);
    CP_COMMIT();
    sampleB2(smem, SM_B0, xpad, b, 0, px, cg);
    CP_WAIT0();
    __syncthreads();

    for (int kb = 0; kb < 72; ++kb) {
        uint32_t acur = (kb & 1) ? SM_A1 : SM_A0;
        uint32_t bcur = (kb & 1) ? SM_B1 : SM_B0;
        uint32_t anx  = (kb & 1) ? SM_A0 : SM_A1;
        uint32_t bnx  = (kb & 1) ? SM_B0 : SM_B1;
        if (kb < 71) {
            stageA2(sb + anx, whi, wlo, kb + 1, tid);
            CP_COMMIT();
            sampleB2(smem, bnx, xpad, b, kb + 1, px, cg);
        }
#pragma unroll
        for (int ks = 0; ks < 2; ++ks) {
            uint32_t ah_[4][4], al_[4][4], bf[2][4];
            int arow0 = m_base + (lane & 15);
            uint32_t acolb = (uint32_t)((ks << 5) + ((lane >> 4) << 4));
#pragma unroll
            for (int mi = 0; mi < 4; ++mi) {
                int row = arow0 + (mi << 4);
                uint32_t o = SW64(row, acolb);
                LDSM4(ah_[mi], sb + acur + o);
                LDSM4(al_[mi], sb + acur + 16384 + o);
            }
            int brow0 = n_base + ((lane >> 4) << 3) + (lane & 7);
            uint32_t bcolb = (uint32_t)((ks << 5) + (((lane >> 3) & 1) << 4));
#pragma unroll
            for (int np = 0; np < 2; ++np) {
                int row = brow0 + (np << 4);
                LDSM4(bf[np], sb + bcur + SW64(row, bcolb));
            }
#pragma unroll
            for (int mi = 0; mi < 4; ++mi)
#pragma unroll
                for (int nj = 0; nj < 4; ++nj) {
                    MMA16816(acc[mi][nj], ah_[mi], bf[nj >> 1][(nj & 1) * 2], bf[nj >> 1][(nj & 1) * 2 + 1]);
                    MMA16816(acc[mi][nj], al_[mi], bf[nj >> 1][(nj & 1) * 2], bf[nj >> 1][(nj & 1) * 2 + 1]);
                }
#pragma unroll
            for (int np = 0; np < 2; ++np) {
                int row = brow0 + (np << 4);
                LDSM4(bf[np], sb + bcur + 8192 + SW64(row, bcolb));
            }
#pragma unroll
            for (int mi = 0; mi < 4; ++mi)
#pragma unroll
                for (int nj = 0; nj < 4; ++nj)
                    MMA16816(acc[mi][nj], ah_[mi], bf[nj >> 1][(nj & 1) * 2], bf[nj >> 1][(nj & 1) * 2 + 1]);
        }
        CP_WAIT0();
        __syncthreads();
    }

    // ---- epilogue: relu + direct v2 stores (padded or flat output) ----
    int plane = pad_out ? PHW : HWSZ;
    int ostride = pad_out ? PW : 64;
    int obase = pad_out ? PBASE : 0;
#pragma unroll
    for (int mi = 0; mi < 4; ++mi) {
#pragma unroll
        for (int nj = 0; nj < 4; ++nj) {
            int row = m_base + (mi << 4) + (lane >> 2);
            int colp = n_base + (nj << 3) + ((lane & 3) << 1);
            int pix = px0 + colp;
            int h = pix >> 6;
            int wv = pix & 63;
            float* d0 = outp + (size_t)(b * 256 + row) * plane + h * ostride + wv + obase;
            float* d1 = outp + (size_t)(b * 256 + row + 8) * plane + h * ostride + wv + obase;
            float2 v0, v1;
            v0.x = fmaxf(acc[mi][nj][0], 0.f);
            v0.y = fmaxf(acc[mi][nj][1], 0.f);
            v1.x = fmaxf(acc[mi][nj][2], 0.f);
            v1.y = fmaxf(acc[mi][nj][3], 0.f);
            *(float2*)d0 = v0;
            *(float2*)d1 = v1;
        }
    }
}

// ---------------- launch ----------------------------------------------------
extern "C" void kernel_launch(void* const* d_in, const int* in_sizes, int n_in,
                              void* d_out, int out_size) {
    (void)in_sizes; (void)n_in; (void)out_size;
    const float* x    = (const float*)d_in[0];
    const float* offw = (const float*)d_in[1];
    const float* offb = (const float*)d_in[2];
    const float* w    = (const float*)d_in[3];
    float* out = (float*)d_out;

    float *padA, *padB;
    __nv_bfloat16 *gwhi, *gwlo, *gowhi, *gowlo;
    cudaGetSymbolAddress((void**)&padA, g_padA);
    cudaGetSymbolAddress((void**)&padB, g_padB);
    cudaGetSymbolAddress((void**)&gwhi, g_whi);
    cudaGetSymbolAddress((void**)&gwlo, g_wlo);
    cudaGetSymbolAddress((void**)&gowhi, g_owhi);
    cudaGetSymbolAddress((void**)&gowlo, g_owlo);

    cudaFuncSetAttribute(fused_layer_kernel,
                         cudaFuncAttributeMaxDynamicSharedMemorySize, SM_TOTAL);

    pad_input_kernel<<<(4734976 + 255) / 256, 256>>>(x, padA, padB);
    prep_w_kernel<<<(2359296 + 255) / 256, 256>>>(w, gwhi, gwlo);
    prep_offw_kernel<<<(294912 + 255) / 256, 256>>>(offw, gowhi, gowlo);

    const float* cur = padA;
    for (int r = 0; r < RB; ++r) {
        int last = (r == 3);
        float* nxt = last ? out : ((r & 1) == 0 ? padB : padA);
        fused_layer_kernel<<<128, 512, SM_TOTAL>>>(
            cur, gowhi + (size_t)r * 73728, gowlo + (size_t)r * 73728,
            offb + r * OC2, gwhi + (size_t)r * 589824, gwlo + (size_t)r * 589824,
            nxt, last ? 0 : 1);
        cur = nxt;
    }
}

// round 9
// speedup vs baseline: 1.0256x; 1.0256x over previous
#include <cuda_runtime.h>
#include <cuda_bf16.h>
#include <math.h>
#include <stdint.h>

#define RB 4
#define CC 256
#define HWSZ 4096
#define OC2 18
#define PW 68
#define PHW 4624            // 68*68
#define PBASE 138           // 2*68 + 2

// ---------------- smem layout (bytes, dynamic) ------------------------------
#define SM_A0   0
#define SM_A1   32768
#define SM_B0   65536
#define SM_B1   81920
#define SM_IDX  98304       // int[1152]
#define SM_WY   102912      // float[1152]
#define SM_WX   107520      // float[1152]
#define SM_TOTAL 112128

// 64B-row swizzle
#define SW64(row, colb) (((uint32_t)(row) << 6) + \
    ((uint32_t)(colb) ^ (((uint32_t)(row) & 3) << 4) ^ (((uint32_t)(row) & 4) << 2)))

// ---------------- scratch ----------------------------------------------------
__device__ float g_padA[4734976];
__device__ float g_padB[4734976];
__device__ __align__(16) __nv_bfloat16 g_whi[2359296];
__device__ __align__(16) __nv_bfloat16 g_wlo[2359296];
__device__ __align__(16) __nv_bfloat16 g_owhi[294912];
__device__ __align__(16) __nv_bfloat16 g_owlo[294912];

// ---------------- PTX helpers ----------------------------------------------
static __device__ __forceinline__ uint32_t smem_u32(const void* p) {
    uint32_t a;
    asm("{ .reg .u64 t; cvta.to.shared.u64 t, %1; cvt.u32.u64 %0, t; }" : "=r"(a) : "l"(p));
    return a;
}

#define LDSM4(r, a) \
    asm volatile("ldmatrix.sync.aligned.m8n8.x4.shared.b16 {%0,%1,%2,%3}, [%4];" \
                 : "=r"((r)[0]), "=r"((r)[1]), "=r"((r)[2]), "=r"((r)[3]) : "r"(a))

#define LDSM2(r, a) \
    asm volatile("ldmatrix.sync.aligned.m8n8.x2.shared.b16 {%0,%1}, [%2];" \
                 : "=r"((r)[0]), "=r"((r)[1]) : "r"(a))

#define MMA16816(c, a, b0, b1) \
    asm volatile("mma.sync.aligned.m16n8k16.row.col.f32.bf16.bf16.f32 " \
                 "{%0,%1,%2,%3}, {%4,%5,%6,%7}, {%8,%9}, {%0,%1,%2,%3};" \
                 : "+f"((c)[0]), "+f"((c)[1]), "+f"((c)[2]), "+f"((c)[3]) \
                 : "r"((a)[0]), "r"((a)[1]), "r"((a)[2]), "r"((a)[3]), \
                   "r"(b0), "r"(b1))

#define CP16(dst, src) \
    asm volatile("cp.async.cg.shared.global [%0], [%1], 16;" :: "r"(dst), "l"(src))
#define CP_COMMIT() asm volatile("cp.async.commit_group;")
#define CP_WAIT0()  asm volatile("cp.async.wait_group 0;")

// ordered-issue scalar global load (read-only path); consumed later
#define LDGF(d, p) asm volatile("ld.global.nc.f32 %0, [%1];" : "=f"(d) : "l"(p))

// ---------------- prep kernels ----------------------------------------------
__global__ void pad_input_kernel(const float* __restrict__ x,
                                 float* __restrict__ pA, float* __restrict__ pB) {
    int i = blockIdx.x * 256 + threadIdx.x;
    if (i >= 4734976) return;
    int plane = i / PHW, rem = i - plane * PHW;
    int h = rem / PW - 2, w = rem % PW - 2;
    float v = 0.f;
    if (h >= 0 && h < 64 && w >= 0 && w < 64) v = x[plane * HWSZ + h * 64 + w];
    pA[i] = v;
    pB[i] = 0.f;
}

__global__ void prep_w_kernel(const float* __restrict__ w,
                              __nv_bfloat16* __restrict__ whi,
                              __nv_bfloat16* __restrict__ wlo) {
    int idx = blockIdx.x * 256 + threadIdx.x;
    if (idx >= 2359296) return;
    int r = idx / 589824;
    int rem = idx - r * 589824;
    int kb = rem >> 13;
    int rem2 = rem & 8191;
    int oc = rem2 >> 5;
    int j = rem2 & 31;
    int kk = kb >> 3;
    int c = ((kb & 7) << 5) + j;
    float v = w[(((r * 256 + oc) * 256 + c) * 9) + kk];
    __nv_bfloat16 h = __float2bfloat16_rn(v);
    whi[idx] = h;
    wlo[idx] = __float2bfloat16_rn(v - __bfloat162float(h));
}

__global__ void prep_offw_kernel(const float* __restrict__ offw,
                                 __nv_bfloat16* __restrict__ owhi,
                                 __nv_bfloat16* __restrict__ owlo) {
    int idx = blockIdx.x * 256 + threadIdx.x;
    if (idx >= 294912) return;
    int r = idx / 73728;
    int rem = idx - r * 73728;
    int kb = rem >> 10;
    int rem2 = rem & 1023;
    int ocp = rem2 >> 5;
    int j = rem2 & 31;
    int kk = kb >> 3;
    int c = ((kb & 7) << 5) + j;
    float v = (ocp < OC2) ? offw[((r * OC2 + ocp) * 256 + c) * 9 + kk] : 0.f;
    __nv_bfloat16 h = __float2bfloat16_rn(v);
    owhi[idx] = h;
    owlo[idx] = __float2bfloat16_rn(v - __bfloat162float(h));
}

// ---------------- staging helpers -------------------------------------------
static __device__ __forceinline__ void stageA2(uint32_t dst,
        const __nv_bfloat16* whi, const __nv_bfloat16* wlo, int kb, int tid) {
    const char* ah = (const char*)whi + ((size_t)kb << 14);
    const char* al = (const char*)wlo + ((size_t)kb << 14);
#pragma unroll
    for (int t = 0; t < 2; ++t) {
        int i = tid + (t << 9);
        uint32_t o = SW64(i >> 2, (i & 3) << 4);
        CP16(dst + o, ah + ((size_t)i << 4));
        CP16(dst + 16384 + o, al + ((size_t)i << 4));
    }
}

static __device__ __forceinline__ void stageA1(uint32_t dst,
        const __nv_bfloat16* owhi, const __nv_bfloat16* owlo, int kb, int tid) {
    if (tid < 128) {
        uint32_t o = SW64(tid >> 2, (tid & 3) << 4);
        CP16(dst + o, (const char*)owhi + ((size_t)kb << 11) + (tid << 4));
        CP16(dst + 16384 + o, (const char*)owlo + ((size_t)kb << 11) + (tid << 4));
    }
}

static __device__ __forceinline__ void cvt_pair(float v0, float v1,
        uint32_t& hp, uint32_t& lp) {
    __nv_bfloat162 h2, l2;
    h2.x = __float2bfloat16_rn(v0);
    h2.y = __float2bfloat16_rn(v1);
    l2.x = __float2bfloat16_rn(v0 - __bfloat162float(h2.x));
    l2.y = __float2bfloat16_rn(v1 - __bfloat162float(h2.y));
    hp = *(uint32_t*)&h2;
    lp = *(uint32_t*)&l2;
}

// full (gather+finish) B staging, used only in prologues
static __device__ __forceinline__ void sampleB1_full(char* smem, uint32_t bbuf,
        const float* __restrict__ xpad, int b, int kb, int px, int cg,
        int hpx, int wpx) {
    int kk = kb >> 3;
    const float* xb = xpad + ((size_t)(b * 256) + ((kb & 7) << 5) + (cg << 3)) * PHW
                    + (hpx + kk / 3 + 1) * PW + (wpx + kk % 3 + 1);
    uint32_t hp[4], lp[4];
#pragma unroll
    for (int jj = 0; jj < 4; ++jj) {
        float v0 = xb[(size_t)(jj << 1) * PHW];
        float v1 = xb[(size_t)((jj << 1) + 1) * PHW];
        cvt_pair(v0, v1, hp[jj], lp[jj]);
    }
    uint32_t o = SW64(px, cg << 4);
    *(uint4*)(smem + bbuf + o) = make_uint4(hp[0], hp[1], hp[2], hp[3]);
    *(uint4*)(smem + bbuf + 8192 + o) = make_uint4(lp[0], lp[1], lp[2], lp[3]);
}

static __device__ __forceinline__ void sampleB2_full(char* smem, uint32_t bbuf,
        const float* __restrict__ xpad, int b, int kb, int px, int cg) {
    int kk = kb >> 3;
    int mi = kk * 128 + px;
    int idx0 = ((const int*)(smem + SM_IDX))[mi];
    float wy = ((const float*)(smem + SM_WY))[mi];
    float wx = ((const float*)(smem + SM_WX))[mi];
    float w01 = (1.f - wy) * wx;
    float w00 = (1.f - wy) - w01;
    float w11 = wy * wx;
    float w10 = wy - w11;
    const float* xb = xpad + ((size_t)(b * 256) + ((kb & 7) << 5) + (cg << 3)) * PHW + idx0;
    uint32_t hp[4], lp[4];
#pragma unroll
    for (int jj = 0; jj < 4; ++jj) {
        const float* p0 = xb + (size_t)(jj << 1) * PHW;
        const float* p1 = p0 + PHW;
        float v0 = fmaf(w11, p0[PW + 1], fmaf(w10, p0[PW], fmaf(w01, p0[1], w00 * p0[0])));
        float v1 = fmaf(w11, p1[PW + 1], fmaf(w10, p1[PW], fmaf(w01, p1[1], w00 * p1[0])));
        cvt_pair(v0, v1, hp[jj], lp[jj]);
    }
    uint32_t o = SW64(px, cg << 4);
    *(uint4*)(smem + bbuf + o) = make_uint4(hp[0], hp[1], hp[2], hp[3]);
    *(uint4*)(smem + bbuf + 8192 + o) = make_uint4(lp[0], lp[1], lp[2], lp[3]);
}

// ---------------- fused layer kernel ----------------------------------------
__global__ __launch_bounds__(512, 1) void fused_layer_kernel(
    const float* __restrict__ xpad,
    const __nv_bfloat16* __restrict__ owhi, const __nv_bfloat16* __restrict__ owlo,
    const float* __restrict__ offbias,
    const __nv_bfloat16* __restrict__ whi, const __nv_bfloat16* __restrict__ wlo,
    float* __restrict__ outp, int pad_out)
{
    extern __shared__ char smem[];
    uint32_t sb = smem_u32(smem);
    int tid = threadIdx.x;
    int lane = tid & 31;
    int wid = tid >> 5;
    int b = blockIdx.x >> 5;
    int px0 = (blockIdx.x & 31) << 7;

    int px = tid & 127;
    int cg = tid >> 7;
    int hpx = (px0 + px) >> 6;
    int wpx = (px0 + px) & 63;

    // ================= PHASE 1: offset conv GEMM (D_off[32][128]) ==========
    float acc1[2][4];
#pragma unroll
    for (int mi = 0; mi < 2; ++mi)
#pragma unroll
        for (int q = 0; q < 4; ++q) acc1[mi][q] = 0.f;

    stageA1(sb + SM_A0, owhi, owlo, 0, tid);
    CP_COMMIT();
    sampleB1_full(smem, SM_B0, xpad, b, 0, px, cg, hpx, wpx);
    CP_WAIT0();
    __syncthreads();

    // per-ks MMA sub-block for phase 1
    auto mma1_ks = [&](uint32_t acur, uint32_t bcur, int ks) {
        uint32_t a1[2][4], bh1[2], bl1[2];
        int n_base = wid << 3;
        int brow = n_base + (lane & 7);
        uint32_t bo = SW64(brow, (ks << 5) + (((lane >> 3) & 1) << 4));
        LDSM2(bh1, sb + bcur + bo);
        LDSM2(bl1, sb + bcur + 8192 + bo);
#pragma unroll
        for (int mi = 0; mi < 2; ++mi) {
            int row = (mi << 4) + (lane & 15);
            uint32_t o = SW64(row, (ks << 5) + ((lane >> 4) << 4));
            LDSM4(a1[mi], sb + acur + 16384 + o);   // lo
        }
#pragma unroll
        for (int mi = 0; mi < 2; ++mi)
            MMA16816(acc1[mi], a1[mi], bh1[0], bh1[1]);
#pragma unroll
        for (int mi = 0; mi < 2; ++mi) {
            int row = (mi << 4) + (lane & 15);
            uint32_t o = SW64(row, (ks << 5) + ((lane >> 4) << 4));
            LDSM4(a1[mi], sb + acur + o);           // hi
        }
#pragma unroll
        for (int mi = 0; mi < 2; ++mi) {
            MMA16816(acc1[mi], a1[mi], bh1[0], bh1[1]);
            MMA16816(acc1[mi], a1[mi], bl1[0], bl1[1]);
        }
    };

    for (int kb = 0; kb < 72; ++kb) {
        uint32_t acur = (kb & 1) ? SM_A1 : SM_A0;
        uint32_t bcur = (kb & 1) ? SM_B1 : SM_B0;
        uint32_t anx  = (kb & 1) ? SM_A0 : SM_A1;
        uint32_t bnx  = (kb & 1) ? SM_B0 : SM_B1;
        bool stage = (kb < 71);
        float gv[8];
        if (stage) {
            stageA1(sb + anx, owhi, owlo, kb + 1, tid);
            CP_COMMIT();
            int kn = kb + 1;
            int kk = kn >> 3;
            const float* xb = xpad + ((size_t)(b * 256) + ((kn & 7) << 5) + (cg << 3)) * PHW
                            + (hpx + kk / 3 + 1) * PW + (wpx + kk % 3 + 1);
#pragma unroll
            for (int jj = 0; jj < 8; ++jj)
                LDGF(gv[jj], xb + (size_t)jj * PHW);
        }
        mma1_ks(acur, bcur, 0);
        mma1_ks(acur, bcur, 1);
        if (stage) {
            uint32_t hp[4], lp[4];
#pragma unroll
            for (int jj = 0; jj < 4; ++jj)
                cvt_pair(gv[jj * 2], gv[jj * 2 + 1], hp[jj], lp[jj]);
            uint32_t o = SW64(px, cg << 4);
            *(uint4*)(smem + bnx + o) = make_uint4(hp[0], hp[1], hp[2], hp[3]);
            *(uint4*)(smem + bnx + 8192 + o) = make_uint4(lp[0], lp[1], lp[2], lp[3]);
        }
        CP_WAIT0();
        __syncthreads();
    }

    // write offsets to smem (reuse SM_B0 region): offs[32][128] f32
    {
        float* offs = (float*)(smem + SM_B0);
#pragma unroll
        for (int mi = 0; mi < 2; ++mi) {
            int ocp = (mi << 4) + (lane >> 2);
            int pc = (wid << 3) + ((lane & 3) << 1);
            offs[ocp * 128 + pc] = acc1[mi][0];
            offs[ocp * 128 + pc + 1] = acc1[mi][1];
            offs[(ocp + 8) * 128 + pc] = acc1[mi][2];
            offs[(ocp + 8) * 128 + pc + 1] = acc1[mi][3];
        }
    }
    __syncthreads();

    // ---- bilinear metadata (padded addressing, clamped) ----
    {
        const float* offs = (const float*)(smem + SM_B0);
        int* sIdx = (int*)(smem + SM_IDX);
        float* sWy = (float*)(smem + SM_WY);
        float* sWx = (float*)(smem + SM_WX);
        for (int i = tid; i < 1152; i += 512) {
            int kk = i >> 7;
            int p = i & 127;
            int pix = px0 + p;
            int h = pix >> 6;
            int w = pix & 63;
            float dy = offs[((2 * kk) << 7) + p] + offbias[2 * kk];
            float dx = offs[((2 * kk + 1) << 7) + p] + offbias[2 * kk + 1];
            float py = fminf(fmaxf((float)(h + kk / 3 - 1) + dy, -1.5f), 64.5f);
            float pxx = fminf(fmaxf((float)(w + kk % 3 - 1) + dx, -1.5f), 64.5f);
            float y0f = floorf(py), x0f = floorf(pxx);
            sIdx[i] = ((int)y0f + 2) * PW + ((int)x0f + 2);
            sWy[i] = py - y0f;
            sWx[i] = pxx - x0f;
        }
    }
    __syncthreads();

    // ================= PHASE 2: deform GEMM (D[256][128]) ==================
    float acc[4][4][4];
#pragma unroll
    for (int mi = 0; mi < 4; ++mi)
#pragma unroll
        for (int nj = 0; nj < 4; ++nj)
#pragma unroll
            for (int q = 0; q < 4; ++q) acc[mi][nj][q] = 0.f;

    int m_base = (wid & 3) << 6;
    int n_base = (wid >> 2) << 5;

    stageA2(sb + SM_A0, whi, wlo, 0, tid);
    CP_COMMIT();
    sampleB2_full(smem, SM_B0, xpad, b, 0, px, cg);
    CP_WAIT0();
    __syncthreads();

    // per-ks MMA sub-block (al·bh, ah·bh, ah·bl ordering: peak regs A16+B8)
    auto mma2_ks = [&](uint32_t acur, uint32_t bcur, int ks) {
        uint32_t a_[4][4], bf[2][4];
        int arow0 = m_base + (lane & 15);
        uint32_t acolb = (uint32_t)((ks << 5) + ((lane >> 4) << 4));
        int brow0 = n_base + ((lane >> 4) << 3) + (lane & 7);
        uint32_t bcolb = (uint32_t)((ks << 5) + (((lane >> 3) & 1) << 4));
#pragma unroll
        for (int np = 0; np < 2; ++np)
            LDSM4(bf[np], sb + bcur + SW64(brow0 + (np << 4), bcolb));
#pragma unroll
        for (int mi = 0; mi < 4; ++mi)
            LDSM4(a_[mi], sb + acur + 16384 + SW64(arow0 + (mi << 4), acolb));  // lo
#pragma unroll
        for (int mi = 0; mi < 4; ++mi)
#pragma unroll
            for (int nj = 0; nj < 4; ++nj)
                MMA16816(acc[mi][nj], a_[mi], bf[nj >> 1][(nj & 1) * 2], bf[nj >> 1][(nj & 1) * 2 + 1]);
#pragma unroll
        for (int mi = 0; mi < 4; ++mi)
            LDSM4(a_[mi], sb + acur + SW64(arow0 + (mi << 4), acolb));          // hi
#pragma unroll
        for (int mi = 0; mi < 4; ++mi)
#pragma unroll
            for (int nj = 0; nj < 4; ++nj)
                MMA16816(acc[mi][nj], a_[mi], bf[nj >> 1][(nj & 1) * 2], bf[nj >> 1][(nj & 1) * 2 + 1]);
#pragma unroll
        for (int np = 0; np < 2; ++np)
            LDSM4(bf[np], sb + bcur + 8192 + SW64(brow0 + (np << 4), bcolb));   // lo B
#pragma unroll
        for (int mi = 0; mi < 4; ++mi)
#pragma unroll
            for (int nj = 0; nj < 4; ++nj)
                MMA16816(acc[mi][nj], a_[mi], bf[nj >> 1][(nj & 1) * 2], bf[nj >> 1][(nj & 1) * 2 + 1]);
    };

    for (int kb = 0; kb < 72; ++kb) {
        uint32_t acur = (kb & 1) ? SM_A1 : SM_A0;
        uint32_t bcur = (kb & 1) ? SM_B1 : SM_B0;
        uint32_t anx  = (kb & 1) ? SM_A0 : SM_A1;
        uint32_t bnx  = (kb & 1) ? SM_B0 : SM_B1;
        bool stage = (kb < 71);
        float g0[16];
        float w00 = 0.f, w01 = 0.f, w10 = 0.f, w11 = 0.f;
        const float* xg = xpad;
        if (stage) {
            stageA2(sb + anx, whi, wlo, kb + 1, tid);
            CP_COMMIT();
            int kn = kb + 1;
            int mi = ((kn >> 3) << 7) + px;
            int idx0 = ((const int*)(smem + SM_IDX))[mi];
            float wy = ((const float*)(smem + SM_WY))[mi];
            float wx = ((const float*)(smem + SM_WX))[mi];
            w01 = (1.f - wy) * wx;
            w00 = (1.f - wy) - w01;
            w11 = wy * wx;
            w10 = wy - w11;
            xg = xpad + ((size_t)(b * 256) + ((kn & 7) << 5) + (cg << 3)) * PHW + idx0;
            // gather group A: channels 0..3 of this thread's 8
#pragma unroll
            for (int jj = 0; jj < 4; ++jj) {
                const float* p = xg + (size_t)jj * PHW;
                LDGF(g0[jj * 4 + 0], p);
                LDGF(g0[jj * 4 + 1], p + 1);
                LDGF(g0[jj * 4 + 2], p + PW);
                LDGF(g0[jj * 4 + 3], p + PW + 1);
            }
        }

        mma2_ks(acur, bcur, 0);

        float g1[16];
        if (stage) {
            // finish group A
            uint32_t hp[2], lp[2];
            float v0 = fmaf(w11, g0[3],  fmaf(w10, g0[2],  fmaf(w01, g0[1],  w00 * g0[0])));
            float v1 = fmaf(w11, g0[7],  fmaf(w10, g0[6],  fmaf(w01, g0[5],  w00 * g0[4])));
            float v2 = fmaf(w11, g0[11], fmaf(w10, g0[10], fmaf(w01, g0[9],  w00 * g0[8])));
            float v3 = fmaf(w11, g0[15], fmaf(w10, g0[14], fmaf(w01, g0[13], w00 * g0[12])));
            cvt_pair(v0, v1, hp[0], lp[0]);
            cvt_pair(v2, v3, hp[1], lp[1]);
            uint32_t o = SW64(px, cg << 4);
            *(uint2*)(smem + bnx + o) = make_uint2(hp[0], hp[1]);
            *(uint2*)(smem + bnx + 8192 + o) = make_uint2(lp[0], lp[1]);
            // gather group B: channels 4..7
#pragma unroll
            for (int jj = 0; jj < 4; ++jj) {
                const float* p = xg + (size_t)(jj + 4) * PHW;
                LDGF(g1[jj * 4 + 0], p);
                LDGF(g1[jj * 4 + 1], p + 1);
                LDGF(g1[jj * 4 + 2], p + PW);
                LDGF(g1[jj * 4 + 3], p + PW + 1);
            }
        }

        mma2_ks(acur, bcur, 1);

        if (stage) {
            uint32_t hp[2], lp[2];
            float v0 = fmaf(w11, g1[3],  fmaf(w10, g1[2],  fmaf(w01, g1[1],  w00 * g1[0])));
            float v1 = fmaf(w11, g1[7],  fmaf(w10, g1[6],  fmaf(w01, g1[5],  w00 * g1[4])));
            float v2 = fmaf(w11, g1[11], fmaf(w10, g1[10], fmaf(w01, g1[9],  w00 * g1[8])));
            float v3 = fmaf(w11, g1[15], fmaf(w10, g1[14], fmaf(w01, g1[13], w00 * g1[12])));
            cvt_pair(v0, v1, hp[0], lp[0]);
            cvt_pair(v2, v3, hp[1], lp[1]);
            uint32_t o = SW64(px, cg << 4) + 8;
            *(uint2*)(smem + bnx + o) = make_uint2(hp[0], hp[1]);
            *(uint2*)(smem + bnx + 8192 + o) = make_uint2(lp[0], lp[1]);
        }
        CP_WAIT0();
        __syncthreads();
    }

    // ---- epilogue: relu + direct v2 stores (padded or flat output) ----
    int plane = pad_out ? PHW : HWSZ;
    int ostride = pad_out ? PW : 64;
    int obase = pad_out ? PBASE : 0;
#pragma unroll
    for (int mi = 0; mi < 4; ++mi) {
#pragma unroll
        for (int nj = 0; nj < 4; ++nj) {
            int row = m_base + (mi << 4) + (lane >> 2);
            int colp = n_base + (nj << 3) + ((lane & 3) << 1);
            int pix = px0 + colp;
            int h = pix >> 6;
            int wv = pix & 63;
            float* d0 = outp + (size_t)(b * 256 + row) * plane + h * ostride + wv + obase;
            float* d1 = outp + (size_t)(b * 256 + row + 8) * plane + h * ostride + wv + obase;
            float2 v0, v1;
            v0.x = fmaxf(acc[mi][nj][0], 0.f);
            v0.y = fmaxf(acc[mi][nj][1], 0.f);
            v1.x = fmaxf(acc[mi][nj][2], 0.f);
            v1.y = fmaxf(acc[mi][nj][3], 0.f);
            *(float2*)d0 = v0;
            *(float2*)d1 = v1;
        }
    }
}

// ---------------- launch ----------------------------------------------------
extern "C" void kernel_launch(void* const* d_in, const int* in_sizes, int n_in,
                              void* d_out, int out_size) {
    (void)in_sizes; (void)n_in; (void)out_size;
    const float* x    = (const float*)d_in[0];
    const float* offw = (const float*)d_in[1];
    const float* offb = (const float*)d_in[2];
    const float* w    = (const float*)d_in[3];
    float* out = (float*)d_out;

    float *padA, *padB;
    __nv_bfloat16 *gwhi, *gwlo, *gowhi, *gowlo;
    cudaGetSymbolAddress((void**)&padA, g_padA);
    cudaGetSymbolAddress((void**)&padB, g_padB);
    cudaGetSymbolAddress((void**)&gwhi, g_whi);
    cudaGetSymbolAddress((void**)&gwlo, g_wlo);
    cudaGetSymbolAddress((void**)&gowhi, g_owhi);
    cudaGetSymbolAddress((void**)&gowlo, g_owlo);

    cudaFuncSetAttribute(fused_layer_kernel,
                         cudaFuncAttributeMaxDynamicSharedMemorySize, SM_TOTAL);

    pad_input_kernel<<<(4734976 + 255) / 256, 256>>>(x, padA, padB);
    prep_w_kernel<<<(2359296 + 255) / 256, 256>>>(w, gwhi, gwlo);
    prep_offw_kernel<<<(294912 + 255) / 256, 256>>>(offw, gowhi, gowlo);

    const float* cur = padA;
    for (int r = 0; r < RB; ++r) {
        int last = (r == 3);
        float* nxt = last ? out : ((r & 1) == 0 ? padB : padA);
        fused_layer_kernel<<<128, 512, SM_TOTAL>>>(
            cur, gowhi + (size_t)r * 73728, gowlo + (size_t)r * 73728,
            offb + r * OC2, gwhi + (size_t)r * 589824, gwlo + (size_t)r * 589824,
            nxt, last ? 0 : 1);
        cur = nxt;
    }
}